// round 7
// baseline (speedup 1.0000x reference)
#include <cuda_runtime.h>

#define DIM 1024
#define NQ 10
#define NL 4
#define WPB 4                          // warps per block, 1 row per warp
#define TROW 34                        // transpose buffer row stride (floats, even!)
#define SWP(i) ((i) + ((i) >> 5))      // stride-33 swizzle for general-path gather

typedef unsigned long long u64;

struct Blob {
    int npasses;
    int ident;
    u64 gdup[NL][NQ][4];   // {v,v} duplicates: g00,g01,g10,g11 (cross-register stages)
    u64 gdiag[NL][NQ][2];  // {g00,g11} and {g01,g10}       (in-register stages)
};

__device__   Blob g_blob;
__constant__ Blob c_blob;
__device__ int g_perm[DIM];

__device__ __forceinline__ u64 pk2(float lo, float hi) {
    u64 r; asm("mov.b64 %0, {%1, %2};" : "=l"(r) : "f"(lo), "f"(hi)); return r;
}
__device__ __forceinline__ void unpk2(u64 v, float& lo, float& hi) {
    asm("mov.b64 {%0, %1}, %2;" : "=f"(lo), "=f"(hi) : "l"(v));
}
__device__ __forceinline__ u64 fma2(u64 a, u64 b, u64 c) {
    u64 d; asm("fma.rn.f32x2 %0, %1, %2, %3;" : "=l"(d) : "l"(a), "l"(b), "l"(c)); return d;
}
__device__ __forceinline__ u64 mul2(u64 a, u64 b) {
    u64 d; asm("mul.rn.f32x2 %0, %1, %2;" : "=l"(d) : "l"(a), "l"(b)); return d;
}
__device__ __forceinline__ u64 swp2(u64 v) {   // swap the two f32 lanes
    u64 r;
    asm("{\n\t.reg .b32 a,b;\n\tmov.b64 {a,b}, %1;\n\tmov.b64 %0, {b,a};\n\t}"
        : "=l"(r) : "l"(v));
    return r;
}
// volatile LDS.64: pinned in place (no hoist/CSE), no global memory barrier.
__device__ __forceinline__ u64 lds64v(const u64* p) {
    u64 v;
    asm volatile("ld.shared.b64 %0, [%1];"
                 : "=l"(v) : "r"((unsigned)__cvta_generic_to_shared(p)));
    return v;
}

// ---------------------------------------------------------------------------
// Prep: perm via diagonal shortcut, identity flag, per-bit gates in both
// packed forms, 4->1 layer composition when perm == identity.
// ---------------------------------------------------------------------------
__global__ void prep_kernel(const float* __restrict__ C,
                            const float* __restrict__ angles) {
    __shared__ int s_ident;
    __shared__ float G[NL][NQ][4];
    int tid = threadIdx.x;
    if (tid == 0) s_ident = 1;
    __syncthreads();

    // permutation-matrix row i: perm[i]=i iff C[i][i] != 0
    {
        int p = tid;
        float d = C[(size_t)tid * DIM + tid];
        if (d == 0.0f) {
            atomicExch(&s_ident, 0);
            const float* row = C + (size_t)tid * DIM;
            for (int j = 0; j < DIM; j++)
                if (row[j] != 0.0f) { p = j; break; }
        }
        g_perm[tid] = p;
    }

    // per-(layer,qubit) gate: G = R(a2/2) @ R(a1/2) @ R(a0/2)
    if (tid < NL * NQ) {
        int l = tid / NQ, q = tid % NQ;
        const float* a = angles + (size_t)(l * NQ + q) * 3;
        float m0 = 1.f, m1 = 0.f, m2 = 0.f, m3 = 1.f;
        #pragma unroll
        for (int k = 0; k < 3; k++) {
            float h = 0.5f * a[k];
            float c = cosf(h), s = sinf(h);
            float n0 = c * m0 - s * m2, n1 = c * m1 - s * m3;
            float n2 = s * m0 + c * m2, n3 = s * m1 + c * m3;
            m0 = n0; m1 = n1; m2 = n2; m3 = n3;
        }
        G[l][q][0] = m0; G[l][q][1] = m1; G[l][q][2] = m2; G[l][q][3] = m3;
    }
    __syncthreads();

    if (s_ident) {
        if (tid < NQ) {   // compose all 4 layers per bit: H_b = G3 G2 G1 G0
            int b = tid, q = 9 - b;
            float m0 = G[0][q][0], m1 = G[0][q][1], m2 = G[0][q][2], m3 = G[0][q][3];
            #pragma unroll
            for (int l = 1; l < NL; l++) {
                float a0 = G[l][q][0], a1 = G[l][q][1], a2 = G[l][q][2], a3 = G[l][q][3];
                float n0 = a0 * m0 + a1 * m2, n1 = a0 * m1 + a1 * m3;
                float n2 = a2 * m0 + a3 * m2, n3 = a2 * m1 + a3 * m3;
                m0 = n0; m1 = n1; m2 = n2; m3 = n3;
            }
            g_blob.gdup[0][b][0] = pk2(m0, m0); g_blob.gdup[0][b][1] = pk2(m1, m1);
            g_blob.gdup[0][b][2] = pk2(m2, m2); g_blob.gdup[0][b][3] = pk2(m3, m3);
            g_blob.gdiag[0][b][0] = pk2(m0, m3);   // {g00, g11}
            g_blob.gdiag[0][b][1] = pk2(m1, m2);   // {g01, g10}
        }
        if (tid == 0) { g_blob.npasses = 1; g_blob.ident = 1; }
    } else {
        if (tid < NL * NQ) {
            int l = tid / NQ, b = tid % NQ, q = 9 - b;
            float m0 = G[l][q][0], m1 = G[l][q][1], m2 = G[l][q][2], m3 = G[l][q][3];
            g_blob.gdup[l][b][0] = pk2(m0, m0); g_blob.gdup[l][b][1] = pk2(m1, m1);
            g_blob.gdup[l][b][2] = pk2(m2, m2); g_blob.gdup[l][b][3] = pk2(m3, m3);
            g_blob.gdiag[l][b][0] = pk2(m0, m3);
            g_blob.gdiag[l][b][1] = pk2(m1, m2);
        }
        if (tid == 0) { g_blob.npasses = NL; g_blob.ident = 0; }
    }
}

// ---------------------------------------------------------------------------
// Main: ONE row per warp, 16 u64 per thread (adjacent-element f32x2 pairs).
// Layout A: r[j] = {v[lane*32+2j], v[lane*32+2j+1]}  -> bit0 in-register,
//           bits 1..4 across registers.
// Layout B: r[j] = {v[(2j)*32+lane], v[(2j+1)*32+lane]} -> bit5 in-register,
//           bits 6..9 across registers.
// In-register stage:  out = {g00,g11}*r + {g01,g10}*swap(r).
// ---------------------------------------------------------------------------
__global__ __launch_bounds__(32 * WPB)
void qnet_kernel(const float* __restrict__ x, float* __restrict__ out, int nrows) {
    __shared__ float tbuf[WPB][32 * TROW];         // 4352 B per warp
    __shared__ u64 sdup[NL][NQ][4];
    __shared__ u64 sdiag[NL][NQ][2];
    __shared__ unsigned short sperm[DIM + DIM / 32];   // general path only

    int tid   = threadIdx.x;
    int np    = c_blob.npasses;
    bool fused = (np == 1) && c_blob.ident;

    for (int i = tid; i < NL * NQ * 4; i += blockDim.x)
        ((u64*)sdup)[i] = ((const u64*)c_blob.gdup)[i];
    for (int i = tid; i < NL * NQ * 2; i += blockDim.x)
        ((u64*)sdiag)[i] = ((const u64*)c_blob.gdiag)[i];
    if (!fused) {
        for (int i = tid; i < DIM; i += blockDim.x)
            sperm[SWP(i)] = (unsigned short)SWP(g_perm[i]);
    }
    __syncthreads();

    int warp = tid >> 5, lane = tid & 31;
    int row  = blockIdx.x * WPB + warp;
    if (row >= nrows) return;
    float* tb = tbuf[warp];

    // ---- load row, layout A: 32 consecutive floats = 16 u64, no packing ----
    u64 r[16];
    {
        const ulonglong2* px = (const ulonglong2*)(x + (size_t)row * DIM + lane * 32);
        #pragma unroll
        for (int m = 0; m < 8; m++) {
            ulonglong2 v = px[m];
            r[2 * m] = v.x; r[2 * m + 1] = v.y;
        }
    }

    for (int p = 0; p < np; p++) {

        // ---- bit 0: in-register ----
        {
            u64 gad = lds64v(&sdiag[p][0][0]);
            u64 gbc = lds64v(&sdiag[p][0][1]);
            #pragma unroll
            for (int j = 0; j < 16; j++)
                r[j] = fma2(gad, r[j], mul2(gbc, swp2(r[j])));
        }
        // ---- bits 1..4: across registers ----
        #pragma unroll
        for (int b = 1; b < 5; b++) {
            const u64* gg = sdup[p][b];
            u64 ga = lds64v(gg + 0), gb = lds64v(gg + 1);
            u64 gc = lds64v(gg + 2), gd = lds64v(gg + 3);
            int m = 1 << (b - 1);
            #pragma unroll
            for (int j0 = 0; j0 < 16; j0++) {
                if (j0 & m) continue;
                int j1 = j0 | m;
                u64 x0 = r[j0], x1 = r[j1];
                r[j0] = fma2(ga, x0, mul2(gb, x1));
                r[j1] = fma2(gc, x0, mul2(gd, x1));
            }
        }

        // ---- transpose A -> B ----
        __syncwarp();
        #pragma unroll
        for (int j = 0; j < 16; j++)          // STS.64, 8B-aligned (TROW even)
            *(u64*)(tb + lane * TROW + 2 * j) = r[j];
        __syncwarp();
        #pragma unroll
        for (int j = 0; j < 16; j++)          // LDS.32 pair-gather, conflict-free
            r[j] = pk2(tb[(2 * j) * TROW + lane], tb[(2 * j + 1) * TROW + lane]);

        // ---- bit 5: in-register ----
        {
            u64 gad = lds64v(&sdiag[p][5][0]);
            u64 gbc = lds64v(&sdiag[p][5][1]);
            #pragma unroll
            for (int j = 0; j < 16; j++)
                r[j] = fma2(gad, r[j], mul2(gbc, swp2(r[j])));
        }
        // ---- bits 6..9: across registers ----
        #pragma unroll
        for (int b = 6; b < 10; b++) {
            const u64* gg = sdup[p][b];
            u64 ga = lds64v(gg + 0), gb = lds64v(gg + 1);
            u64 gc = lds64v(gg + 2), gd = lds64v(gg + 3);
            int m = 1 << (b - 6);
            #pragma unroll
            for (int j0 = 0; j0 < 16; j0++) {
                if (j0 & m) continue;
                int j1 = j0 | m;
                u64 x0 = r[j0], x1 = r[j1];
                r[j0] = fma2(ga, x0, mul2(gb, x1));
                r[j1] = fma2(gc, x0, mul2(gd, x1));
            }
        }

        if (fused) break;   // store directly from layout B below

        // ---- general path: B -> A with perm folded into the gather ----
        __syncwarp();
        #pragma unroll
        for (int j = 0; j < 16; j++) {
            float lo, hi; unpk2(r[j], lo, hi);
            tb[SWP((2 * j) * 32 + lane)]     = lo;
            tb[SWP((2 * j + 1) * 32 + lane)] = hi;
        }
        __syncwarp();
        #pragma unroll
        for (int j = 0; j < 16; j++) {
            int i0 = lane * 32 + 2 * j;
            r[j] = pk2(tb[sperm[SWP(i0)]], tb[sperm[SWP(i0 + 1)]]);
        }
    }

    if (fused) {
        // store layout B: for each j, warp writes 2 coalesced 128B lines
        float* o = out + (size_t)row * DIM + lane;
        #pragma unroll
        for (int j = 0; j < 16; j++) {
            float lo, hi; unpk2(r[j], lo, hi);
            o[(2 * j) * 32]     = lo;
            o[(2 * j + 1) * 32] = hi;
        }
    } else {
        // store layout A: contiguous, 8x STG.128
        ulonglong2* po = (ulonglong2*)(out + (size_t)row * DIM + lane * 32);
        #pragma unroll
        for (int m = 0; m < 8; m++) {
            ulonglong2 v; v.x = r[2 * m]; v.y = r[2 * m + 1];
            po[m] = v;
        }
    }
}

// ---------------------------------------------------------------------------
extern "C" void kernel_launch(void* const* d_in, const int* in_sizes, int n_in,
                              void* d_out, int out_size) {
    const float* x      = (const float*)d_in[0];   // [BATCH, 1024]
    const float* angles = (const float*)d_in[1];   // [4, 10, 3]
    const float* cnot   = (const float*)d_in[2];   // [1024, 1024]
    float* out = (float*)d_out;

    int nrows = in_sizes[0] / DIM;

    prep_kernel<<<1, DIM>>>(cnot, angles);

    // copy computed blob into __constant__ (D2D async: graph-capturable)
    void* blob_dev = nullptr;
    cudaGetSymbolAddress(&blob_dev, g_blob);
    cudaMemcpyToSymbolAsync(c_blob, blob_dev, sizeof(Blob), 0,
                            cudaMemcpyDeviceToDevice, 0);

    int nblocks = (nrows + WPB - 1) / WPB;
    qnet_kernel<<<nblocks, 32 * WPB>>>(x, out, nrows);
}

// round 8
// speedup vs baseline: 1.0830x; 1.0830x over previous
#include <cuda_runtime.h>

#define DIM 1024
#define NQ 10
#define NL 4
#define WPB 4                          // warps per block (each warp = 2 rows)
#define TR 34                          // transpose stride in u64 (even -> STS.128 ok)
#define SWP(i) ((i) + ((i) >> 5))      // stride-33 swizzle (sperm indexing only)

typedef unsigned long long u64;

struct Blob {
    int npasses;
    int ident;
    u64 g[NL][NQ][4];   // packed f32x2 {v,v}: g00,g01,g10,g11
};

__device__ Blob g_blob;
__device__ int  g_perm[DIM];

__device__ __forceinline__ u64 pk2(float lo, float hi) {
    u64 r; asm("mov.b64 %0, {%1, %2};" : "=l"(r) : "f"(lo), "f"(hi)); return r;
}
__device__ __forceinline__ void unpk2(u64 v, float& lo, float& hi) {
    asm("mov.b64 {%0, %1}, %2;" : "=f"(lo), "=f"(hi) : "l"(v));
}
__device__ __forceinline__ u64 fma2(u64 a, u64 b, u64 c) {
    u64 d; asm("fma.rn.f32x2 %0, %1, %2, %3;" : "=l"(d) : "l"(a), "l"(b), "l"(c)); return d;
}
__device__ __forceinline__ u64 mul2(u64 a, u64 b) {
    u64 d; asm("mul.rn.f32x2 %0, %1, %2;" : "=l"(d) : "l"(a), "l"(b)); return d;
}
// volatile LDS.128 (2x u64): pinned in place, no hoist into registers,
// no global memory-clobber -> FMA scheduling stays free.
__device__ __forceinline__ void lds128v(const u64* p, u64& a, u64& b) {
    asm volatile("ld.shared.v2.u64 {%0, %1}, [%2];"
                 : "=l"(a), "=l"(b)
                 : "r"((unsigned)__cvta_generic_to_shared(p)));
}

// ---------------------------------------------------------------------------
// Prep: perm via diagonal shortcut, identity flag, per-bit gates (packed u64),
// 4->1 layer composition when perm == identity. One block, 1024 threads.
// ---------------------------------------------------------------------------
__global__ void prep_kernel(const float* __restrict__ C,
                            const float* __restrict__ angles) {
    __shared__ int s_ident;
    __shared__ float G[NL][NQ][4];
    int tid = threadIdx.x;
    if (tid == 0) s_ident = 1;
    __syncthreads();

    // permutation-matrix row i: perm[i]=i iff C[i][i] != 0
    {
        int p = tid;
        float d = C[(size_t)tid * DIM + tid];
        if (d == 0.0f) {
            atomicExch(&s_ident, 0);
            const float* row = C + (size_t)tid * DIM;
            for (int j = 0; j < DIM; j++)
                if (row[j] != 0.0f) { p = j; break; }
        }
        g_perm[tid] = p;
    }

    // per-(layer,qubit) gate: G = R(a2/2) @ R(a1/2) @ R(a0/2)
    if (tid < NL * NQ) {
        int l = tid / NQ, q = tid % NQ;
        const float* a = angles + (size_t)(l * NQ + q) * 3;
        float m0 = 1.f, m1 = 0.f, m2 = 0.f, m3 = 1.f;
        #pragma unroll
        for (int k = 0; k < 3; k++) {
            float h = 0.5f * a[k];
            float c = cosf(h), s = sinf(h);
            float n0 = c * m0 - s * m2, n1 = c * m1 - s * m3;
            float n2 = s * m0 + c * m2, n3 = s * m1 + c * m3;
            m0 = n0; m1 = n1; m2 = n2; m3 = n3;
        }
        G[l][q][0] = m0; G[l][q][1] = m1; G[l][q][2] = m2; G[l][q][3] = m3;
    }
    __syncthreads();

    if (s_ident) {
        if (tid < NQ) {   // compose all 4 layers per bit: H_b = G3 G2 G1 G0
            int b = tid, q = 9 - b;
            float m0 = G[0][q][0], m1 = G[0][q][1], m2 = G[0][q][2], m3 = G[0][q][3];
            #pragma unroll
            for (int l = 1; l < NL; l++) {
                float a0 = G[l][q][0], a1 = G[l][q][1], a2 = G[l][q][2], a3 = G[l][q][3];
                float n0 = a0 * m0 + a1 * m2, n1 = a0 * m1 + a1 * m3;
                float n2 = a2 * m0 + a3 * m2, n3 = a2 * m1 + a3 * m3;
                m0 = n0; m1 = n1; m2 = n2; m3 = n3;
            }
            g_blob.g[0][b][0] = pk2(m0, m0); g_blob.g[0][b][1] = pk2(m1, m1);
            g_blob.g[0][b][2] = pk2(m2, m2); g_blob.g[0][b][3] = pk2(m3, m3);
        }
        if (tid == 0) { g_blob.npasses = 1; g_blob.ident = 1; }
    } else {
        if (tid < NL * NQ) {
            int l = tid / NQ, b = tid % NQ, q = 9 - b;
            g_blob.g[l][b][0] = pk2(G[l][q][0], G[l][q][0]);
            g_blob.g[l][b][1] = pk2(G[l][q][1], G[l][q][1]);
            g_blob.g[l][b][2] = pk2(G[l][q][2], G[l][q][2]);
            g_blob.g[l][b][3] = pk2(G[l][q][3], G[l][q][3]);
        }
        if (tid == 0) { g_blob.npasses = NL; g_blob.ident = 0; }
    }
}

// ---------------------------------------------------------------------------
// Main: one warp per TWO rows, f32x2 packed butterflies (rows in the 2 lanes).
// Coefficients in smem, fetched per-stage via volatile LDS.128 pairs.
// Layout A: r[k] = v[lane*32 + k]  (bits 0..4 intra-thread)
// Layout B: r[k] = v[k*32 + lane]  (bits 5..9 intra-thread)
// Transpose buffer: element a*32+b stored at u64 index a*34+b.
//   write (layout A regs):  STS.128 at lane*34 + {k,k+1}   -- conflict-free
//   read  (layout B regs):  LDS.64  at k*34 + lane         -- conflict-free
// Fused path: load A -> bits 0-4 -> transpose -> bits 5-9 -> store B.
// ---------------------------------------------------------------------------
__global__ __launch_bounds__(32 * WPB)
void qnet_kernel(const float* __restrict__ x, float* __restrict__ out, int nrows) {
    __shared__ __align__(16) u64 buf[WPB][32 * TR];     // 8704 B per warp
    __shared__ __align__(16) u64 sdup[NL][NQ][4];
    __shared__ int sperm[DIM + DIM / 32];               // general path only

    int tid   = threadIdx.x;
    int np    = g_blob.npasses;
    bool fused = (np == 1) && g_blob.ident;

    for (int i = tid; i < NL * NQ * 4; i += blockDim.x)
        ((u64*)sdup)[i] = ((const u64*)g_blob.g)[i];
    if (!fused) {
        for (int i = tid; i < DIM; i += blockDim.x) {
            int p = g_perm[i];
            sperm[SWP(i)] = (p >> 5) * TR + (p & 31);   // u64 index in buf
        }
    }
    __syncthreads();

    int warp = tid >> 5, lane = tid & 31;
    int pairi = blockIdx.x * WPB + warp;
    int row0 = pairi * 2;
    if (row0 >= nrows) return;
    int row1 = (row0 + 1 < nrows) ? row0 + 1 : row0;
    u64* wb = buf[warp];

    // ---- load both rows, layout A, pack {row0, row1} into f32x2 ----
    u64 r[32];
    {
        const float4* p0 = (const float4*)(x + (size_t)row0 * DIM + lane * 32);
        const float4* p1 = (const float4*)(x + (size_t)row1 * DIM + lane * 32);
        #pragma unroll
        for (int k4 = 0; k4 < 8; k4++) {
            float4 v0 = p0[k4], v1 = p1[k4];
            r[k4 * 4 + 0] = pk2(v0.x, v1.x);
            r[k4 * 4 + 1] = pk2(v0.y, v1.y);
            r[k4 * 4 + 2] = pk2(v0.z, v1.z);
            r[k4 * 4 + 3] = pk2(v0.w, v1.w);
        }
    }

    for (int p = 0; p < np; p++) {

        // ---- bits 0..4 (intra-thread, layout A) ----
        #pragma unroll
        for (int b = 0; b < 5; b++) {
            const u64* gg = sdup[p][b];
            u64 ga, gb, gc, gd;
            lds128v(gg + 0, ga, gb);
            lds128v(gg + 2, gc, gd);
            int m = 1 << b;
            #pragma unroll
            for (int k0 = 0; k0 < 32; k0++) {
                if (k0 & m) continue;
                int k1 = k0 | m;
                u64 x0 = r[k0], x1 = r[k1];
                r[k0] = fma2(ga, x0, mul2(gb, x1));
                r[k1] = fma2(gc, x0, mul2(gd, x1));
            }
        }

        // ---- transpose A -> B ----
        __syncwarp();
        #pragma unroll
        for (int k = 0; k < 32; k += 2) {          // 16x STS.128
            ulonglong2 v; v.x = r[k]; v.y = r[k + 1];
            *(ulonglong2*)(wb + lane * TR + k) = v;
        }
        __syncwarp();
        #pragma unroll
        for (int k = 0; k < 32; k++)               // 32x LDS.64
            r[k] = wb[k * TR + lane];

        // ---- bits 5..9 (intra-thread, layout B) ----
        #pragma unroll
        for (int b = 5; b < 10; b++) {
            const u64* gg = sdup[p][b];
            u64 ga, gb, gc, gd;
            lds128v(gg + 0, ga, gb);
            lds128v(gg + 2, gc, gd);
            int m = 1 << (b - 5);
            #pragma unroll
            for (int k0 = 0; k0 < 32; k0++) {
                if (k0 & m) continue;
                int k1 = k0 | m;
                u64 x0 = r[k0], x1 = r[k1];
                r[k0] = fma2(ga, x0, mul2(gb, x1));
                r[k1] = fma2(gc, x0, mul2(gd, x1));
            }
        }

        if (fused) break;   // store directly from layout B below

        // ---- general path: B -> A with perm folded into the gather ----
        __syncwarp();
        #pragma unroll
        for (int k = 0; k < 32; k++)               // element k*32+lane at k*TR+lane
            wb[k * TR + lane] = r[k];
        __syncwarp();
        #pragma unroll
        for (int k = 0; k < 32; k++)
            r[k] = wb[sperm[SWP(lane * 32 + k)]];
    }

    if (fused) {
        // store layout B: element i = k*32+lane, coalesced STG.32 per k
        float* o0 = out + (size_t)row0 * DIM + lane;
        float* o1 = out + (size_t)row1 * DIM + lane;
        #pragma unroll
        for (int k = 0; k < 32; k++) {
            float lo, hi; unpk2(r[k], lo, hi);
            o0[k * 32] = lo;
            o1[k * 32] = hi;
        }
    } else {
        // store layout A: 8x STG.128 per row
        float4* o0 = (float4*)(out + (size_t)row0 * DIM + lane * 32);
        float4* o1 = (float4*)(out + (size_t)row1 * DIM + lane * 32);
        #pragma unroll
        for (int k4 = 0; k4 < 8; k4++) {
            float4 v0, v1;
            unpk2(r[k4 * 4 + 0], v0.x, v1.x);
            unpk2(r[k4 * 4 + 1], v0.y, v1.y);
            unpk2(r[k4 * 4 + 2], v0.z, v1.z);
            unpk2(r[k4 * 4 + 3], v0.w, v1.w);
            o0[k4] = v0; o1[k4] = v1;
        }
    }
}

// ---------------------------------------------------------------------------
extern "C" void kernel_launch(void* const* d_in, const int* in_sizes, int n_in,
                              void* d_out, int out_size) {
    const float* x      = (const float*)d_in[0];   // [BATCH, 1024]
    const float* angles = (const float*)d_in[1];   // [4, 10, 3]
    const float* cnot   = (const float*)d_in[2];   // [1024, 1024]
    float* out = (float*)d_out;

    int nrows = in_sizes[0] / DIM;

    prep_kernel<<<1, DIM>>>(cnot, angles);

    int npairs  = (nrows + 1) / 2;
    int nblocks = (npairs + WPB - 1) / WPB;
    qnet_kernel<<<nblocks, 32 * WPB>>>(x, out, nrows);
}